// round 9
// baseline (speedup 1.0000x reference)
#include <cuda_runtime.h>
#include <cuda_bf16.h>
#include <cstdint>
#include <cstddef>

// Problem constants
#define S_LEN 4096
#define HID   4096
#define NQ    32
#define NKV   8
#define HD    128
#define QKV_N 6144              // NQ*HD + 2*NKV*HD
#define K_OFF 4096              // NQ*HD
#define V_OFF 5120              // NQ*HD + NKV*HD
#define SCALE_F 0.08838834764831843f   // 128^-0.5

// Scratch (allocations forbidden -> device globals)
__device__ float g_qkv[(size_t)S_LEN * QKV_N];   // ~100.7 MB
__device__ float g_attn[(size_t)S_LEN * HID];    // ~67 MB

// ---------------------------------------------------------------------------
// SGEMM: C[M,N] = A[M,K] @ B[K,N], all fp32 row-major.
// 128x128 tile, BK=16, 256 threads, 8x8 per thread.
// Double-buffered smem: gmem fetch of tile t+1 overlaps compute on tile t.
// Accumulation order identical to the single-buffered version (same numerics).
// ---------------------------------------------------------------------------
#define BM 128
#define BN 128
#define BK 16

__global__ __launch_bounds__(256) void sgemm_kernel(
    const float* __restrict__ A, const float* __restrict__ B,
    float* __restrict__ C, int M, int N, int K)
{
    __shared__ float As[2][BK][BM + 4];
    __shared__ float Bs[2][BK][BN + 4];

    const int tid = threadIdx.x;
    const int tx = tid & 15;          // 0..15 -> N
    const int ty = tid >> 4;          // 0..15 -> M
    const int bx = blockIdx.x;        // N tile
    const int by = blockIdx.y;        // M tile

    const float* Ab = A + (size_t)by * BM * K;
    const float* Bb = B + (size_t)bx * BN;

    // load mapping
    const int aRow = tid >> 2;            // 0..63
    const int aCol = (tid & 3) << 2;      // 0,4,8,12
    const int bRow = tid >> 5;            // 0..7
    const int bCol = (tid & 31) << 2;     // 0..124

    float acc[8][8];
#pragma unroll
    for (int i = 0; i < 8; i++)
#pragma unroll
        for (int j = 0; j < 8; j++) acc[i][j] = 0.f;

    // prologue: stage tile 0 into buffer 0
    {
        float4 a0 = *(const float4*)(Ab + (size_t)aRow * K + aCol);
        float4 a1 = *(const float4*)(Ab + (size_t)(aRow + 64) * K + aCol);
        float4 b0 = *(const float4*)(Bb + (size_t)bRow * N + bCol);
        float4 b1 = *(const float4*)(Bb + (size_t)(bRow + 8) * N + bCol);
        As[0][aCol + 0][aRow] = a0.x; As[0][aCol + 1][aRow] = a0.y;
        As[0][aCol + 2][aRow] = a0.z; As[0][aCol + 3][aRow] = a0.w;
        As[0][aCol + 0][aRow + 64] = a1.x; As[0][aCol + 1][aRow + 64] = a1.y;
        As[0][aCol + 2][aRow + 64] = a1.z; As[0][aCol + 3][aRow + 64] = a1.w;
        *(float4*)&Bs[0][bRow][bCol]     = b0;
        *(float4*)&Bs[0][bRow + 8][bCol] = b1;
    }
    __syncthreads();

    int cur = 0;
#pragma unroll 1
    for (int k0 = 0; k0 < K; k0 += BK) {
        const int kn = k0 + BK;
        float4 na0, na1, nb0, nb1;
        const bool have_next = (kn < K);
        if (have_next) {
            na0 = *(const float4*)(Ab + (size_t)aRow * K + kn + aCol);
            na1 = *(const float4*)(Ab + (size_t)(aRow + 64) * K + kn + aCol);
            nb0 = *(const float4*)(Bb + (size_t)(kn + bRow) * N + bCol);
            nb1 = *(const float4*)(Bb + (size_t)(kn + bRow + 8) * N + bCol);
        }

#pragma unroll
        for (int k = 0; k < BK; k++) {
            float a[8], b[8];
            *(float4*)&a[0] = *(const float4*)&As[cur][k][ty * 8];
            *(float4*)&a[4] = *(const float4*)&As[cur][k][ty * 8 + 4];
            *(float4*)&b[0] = *(const float4*)&Bs[cur][k][tx * 8];
            *(float4*)&b[4] = *(const float4*)&Bs[cur][k][tx * 8 + 4];
#pragma unroll
            for (int i = 0; i < 8; i++)
#pragma unroll
                for (int j = 0; j < 8; j++)
                    acc[i][j] = fmaf(a[i], b[j], acc[i][j]);
        }

        if (have_next) {
            const int nxt = cur ^ 1;
            As[nxt][aCol + 0][aRow] = na0.x; As[nxt][aCol + 1][aRow] = na0.y;
            As[nxt][aCol + 2][aRow] = na0.z; As[nxt][aCol + 3][aRow] = na0.w;
            As[nxt][aCol + 0][aRow + 64] = na1.x; As[nxt][aCol + 1][aRow + 64] = na1.y;
            As[nxt][aCol + 2][aRow + 64] = na1.z; As[nxt][aCol + 3][aRow + 64] = na1.w;
            *(float4*)&Bs[nxt][bRow][bCol]     = nb0;
            *(float4*)&Bs[nxt][bRow + 8][bCol] = nb1;
        }
        __syncthreads();
        cur ^= 1;
    }

    float* Cb = C + (size_t)(by * BM + ty * 8) * N + bx * BN + tx * 8;
#pragma unroll
    for (int i = 0; i < 8; i++) {
        float4 c0 = make_float4(acc[i][0], acc[i][1], acc[i][2], acc[i][3]);
        float4 c1 = make_float4(acc[i][4], acc[i][5], acc[i][6], acc[i][7]);
        *(float4*)(Cb + (size_t)i * N)     = c0;
        *(float4*)(Cb + (size_t)i * N + 4) = c1;
    }
}

// ---------------------------------------------------------------------------
// RoPE in-place on q (32 heads) and k (8 heads) inside g_qkv.
// Matches jax: inv_freq[j] = 10000^(-j/64), j in [0,64); rotate-half form.
// ---------------------------------------------------------------------------
__global__ void rope_kernel(float* __restrict__ qkv,
                            const int* __restrict__ positions)
{
    int idx = blockIdx.x * blockDim.x + threadIdx.x;
    const int total = S_LEN * (NQ + NKV) * 64;
    if (idx >= total) return;
    int j = idx & 63;
    int t = idx >> 6;
    int head = t % (NQ + NKV);
    int s = t / (NQ + NKV);
    int col = (head < NQ) ? head * HD : K_OFF + (head - NQ) * HD;
    float* base = qkv + (size_t)s * QKV_N + col;

    float inv = powf(10000.0f, -((float)j) / 64.0f);
    float ang = (float)positions[s] * inv;
    float sn, cs;
    sincosf(ang, &sn, &cs);
    float x1 = base[j];
    float x2 = base[j + 64];
    base[j]      = x1 * cs - x2 * sn;
    base[j + 64] = x2 * cs + x1 * sn;
}

// ---------------------------------------------------------------------------
// Flash attention, fp32, causal, GQA (4 q heads per kv head).
// Block: 256 threads, grid (S/64, NQ). BM=BN=64, D=128.
// Thread (ty,tx): scores 4x4 block; O accum 4 rows x 8 D-cols.
// ---------------------------------------------------------------------------
#define FA_LD 132   // 128 + 4 pad

struct FaSmem {
    float Qs[64][FA_LD];
    float Ks[64][FA_LD];
    float Vs[64][FA_LD];
    float Ps[64][68];
    int   pq[64];
    int   pk[64];
};

__global__ __launch_bounds__(256) void flash_kernel(
    const float* __restrict__ qkv, const int* __restrict__ positions,
    float* __restrict__ attn)
{
    extern __shared__ char smem_raw[];
    FaSmem& sm = *reinterpret_cast<FaSmem*>(smem_raw);

    const int tid = threadIdx.x;
    const int tx = tid & 15;
    const int ty = tid >> 4;
    const int qb = blockIdx.x * 64;
    const int qh = blockIdx.y;
    const int kvh = qh >> 2;

    // Load Q tile [64,128]
    {
        const float* qbase = qkv + (size_t)qb * QKV_N + qh * HD;
        for (int i = tid; i < 64 * 32; i += 256) {
            int r = i >> 5, c4 = (i & 31) << 2;
            *(float4*)&sm.Qs[r][c4] = *(const float4*)(qbase + (size_t)r * QKV_N + c4);
        }
        if (tid < 64) sm.pq[tid] = positions[qb + tid];
    }

    float O[4][8];
    float mi[4], li[4];
#pragma unroll
    for (int i = 0; i < 4; i++) {
        mi[i] = -1e30f; li[i] = 0.f;
#pragma unroll
        for (int d = 0; d < 8; d++) O[i][d] = 0.f;
    }

    const int ntiles = (qb >> 6) + 1;
#pragma unroll 1
    for (int t = 0; t < ntiles; t++) {
        const int kb = t * 64;
        __syncthreads();  // protect Ks/Vs/Ps (and Qs on t==0) before overwrite
        {
            const float* kbase = qkv + (size_t)kb * QKV_N + K_OFF + kvh * HD;
            const float* vbase = qkv + (size_t)kb * QKV_N + V_OFF + kvh * HD;
            for (int i = tid; i < 64 * 32; i += 256) {
                int r = i >> 5, c4 = (i & 31) << 2;
                *(float4*)&sm.Ks[r][c4] = *(const float4*)(kbase + (size_t)r * QKV_N + c4);
                *(float4*)&sm.Vs[r][c4] = *(const float4*)(vbase + (size_t)r * QKV_N + c4);
            }
            if (tid < 64) sm.pk[tid] = positions[kb + tid];
        }
        __syncthreads();

        // --- scores S = Q K^T (4x4 per thread) ---
        float s[4][4];
#pragma unroll
        for (int i = 0; i < 4; i++)
#pragma unroll
            for (int j = 0; j < 4; j++) s[i][j] = 0.f;

#pragma unroll 4
        for (int k4 = 0; k4 < 32; k4++) {
            float4 q[4], k[4];
#pragma unroll
            for (int i = 0; i < 4; i++) q[i] = *(const float4*)&sm.Qs[ty * 4 + i][k4 * 4];
#pragma unroll
            for (int j = 0; j < 4; j++) k[j] = *(const float4*)&sm.Ks[tx * 4 + j][k4 * 4];
#pragma unroll
            for (int i = 0; i < 4; i++)
#pragma unroll
                for (int j = 0; j < 4; j++) {
                    s[i][j] = fmaf(q[i].x, k[j].x, s[i][j]);
                    s[i][j] = fmaf(q[i].y, k[j].y, s[i][j]);
                    s[i][j] = fmaf(q[i].z, k[j].z, s[i][j]);
                    s[i][j] = fmaf(q[i].w, k[j].w, s[i][j]);
                }
        }

        // --- mask + online softmax (row stats reduced over 16 tx lanes) ---
#pragma unroll
        for (int i = 0; i < 4; i++) {
            const int prow = sm.pq[ty * 4 + i];
            float m = -1e30f;
#pragma unroll
            for (int j = 0; j < 4; j++) {
                bool ok = (sm.pk[tx * 4 + j] <= prow);
                s[i][j] = ok ? s[i][j] * SCALE_F : -1e30f;
                m = fmaxf(m, s[i][j]);
            }
#pragma unroll
            for (int off = 8; off > 0; off >>= 1)
                m = fmaxf(m, __shfl_xor_sync(0xffffffffu, m, off));

            float mn = fmaxf(mi[i], m);
            float corr = __expf(mi[i] - mn);
            mi[i] = mn;

            float rs = 0.f;
#pragma unroll
            for (int j = 0; j < 4; j++) {
                float p = __expf(s[i][j] - mn);
                sm.Ps[ty * 4 + i][tx * 4 + j] = p;
                rs += p;
            }
#pragma unroll
            for (int off = 8; off > 0; off >>= 1)
                rs += __shfl_xor_sync(0xffffffffu, rs, off);

            li[i] = li[i] * corr + rs;
#pragma unroll
            for (int d = 0; d < 8; d++) O[i][d] *= corr;
        }
        __syncthreads();

        // --- O += P @ V ---
#pragma unroll 4
        for (int c = 0; c < 64; c++) {
            float4 v0 = *(const float4*)&sm.Vs[c][tx * 8];
            float4 v1 = *(const float4*)&sm.Vs[c][tx * 8 + 4];
#pragma unroll
            for (int i = 0; i < 4; i++) {
                float p = sm.Ps[ty * 4 + i][c];
                O[i][0] = fmaf(p, v0.x, O[i][0]);
                O[i][1] = fmaf(p, v0.y, O[i][1]);
                O[i][2] = fmaf(p, v0.z, O[i][2]);
                O[i][3] = fmaf(p, v0.w, O[i][3]);
                O[i][4] = fmaf(p, v1.x, O[i][4]);
                O[i][5] = fmaf(p, v1.y, O[i][5]);
                O[i][6] = fmaf(p, v1.z, O[i][6]);
                O[i][7] = fmaf(p, v1.w, O[i][7]);
            }
        }
    }

    // epilogue: normalize and write to attn[s, qh*128 + d]
#pragma unroll
    for (int i = 0; i < 4; i++) {
        float inv = 1.0f / li[i];
        float* dst = attn + (size_t)(qb + ty * 4 + i) * HID + qh * HD + tx * 8;
        float4 o0 = make_float4(O[i][0] * inv, O[i][1] * inv, O[i][2] * inv, O[i][3] * inv);
        float4 o1 = make_float4(O[i][4] * inv, O[i][5] * inv, O[i][6] * inv, O[i][7] * inv);
        *(float4*)dst       = o0;
        *(float4*)(dst + 4) = o1;
    }
}

// ---------------------------------------------------------------------------
// launch
// ---------------------------------------------------------------------------
extern "C" void kernel_launch(void* const* d_in, const int* in_sizes, int n_in,
                              void* d_out, int out_size)
{
    const int*   positions = (const int*)d_in[0];
    const float* hidden    = (const float*)d_in[1];
    const float* w_qkv     = (const float*)d_in[2];
    const float* w_o       = (const float*)d_in[3];
    float*       out       = (float*)d_out;

    float *qkv = nullptr, *attn = nullptr;
    cudaGetSymbolAddress((void**)&qkv,  g_qkv);
    cudaGetSymbolAddress((void**)&attn, g_attn);

    // 1) QKV projection: [4096,4096] @ [4096,6144]
    sgemm_kernel<<<dim3(QKV_N / BN, S_LEN / BM), 256>>>(
        hidden, w_qkv, qkv, S_LEN, QKV_N, HID);

    // 2) RoPE on q and k in place
    {
        int total = S_LEN * (NQ + NKV) * 64;
        rope_kernel<<<(total + 255) / 256, 256>>>(qkv, positions);
    }

    // 3) Flash attention
    {
        size_t smem = sizeof(FaSmem);
        cudaFuncSetAttribute(flash_kernel,
                             cudaFuncAttributeMaxDynamicSharedMemorySize,
                             (int)smem);
        flash_kernel<<<dim3(S_LEN / 64, NQ), 256, smem>>>(qkv, positions, attn);
    }

    // 4) Output projection: [4096,4096] @ [4096,4096]
    sgemm_kernel<<<dim3(HID / BN, S_LEN / BM), 256>>>(
        attn, w_o, out, S_LEN, HID, HID);
}

// round 11
// speedup vs baseline: 1.3632x; 1.3632x over previous
#include <cuda_runtime.h>
#include <cuda_bf16.h>
#include <cstdint>
#include <cstddef>

// Problem constants
#define S_LEN 4096
#define HID   4096
#define NQ    32
#define NKV   8
#define HD    128
#define QKV_N 6144              // NQ*HD + 2*NKV*HD
#define K_OFF 4096              // NQ*HD
#define V_OFF 5120              // NQ*HD + NKV*HD
#define SCALE_F 0.08838834764831843f   // 128^-0.5

// Scratch (allocations forbidden -> device globals)
__device__ float g_qkv[(size_t)S_LEN * QKV_N];   // ~100.7 MB
__device__ float g_attn[(size_t)S_LEN * HID];    // ~67 MB
// bf16 hi/lo transposed weights: [N][K] layout, K = 4096
__device__ __nv_bfloat16 g_bh_qkv[(size_t)QKV_N * HID];
__device__ __nv_bfloat16 g_bl_qkv[(size_t)QKV_N * HID];
__device__ __nv_bfloat16 g_bh_o[(size_t)HID * HID];
__device__ __nv_bfloat16 g_bl_o[(size_t)HID * HID];

// ---------------------------------------------------------------------------
// mma.sync bf16 (arch-agnostic tensor path; valid on plain sm_103 PTX target)
// D[16x8] f32 += A[16x16] bf16 (row) @ B[16x8] bf16 (col)
// ---------------------------------------------------------------------------
__device__ __forceinline__ void mma_bf16(float* c, const uint32_t* a,
                                         const uint32_t* b)
{
    asm volatile(
        "mma.sync.aligned.m16n8k16.row.col.f32.bf16.bf16.f32 "
        "{%0,%1,%2,%3}, {%4,%5,%6,%7}, {%8,%9}, {%0,%1,%2,%3};\n"
        : "+f"(c[0]), "+f"(c[1]), "+f"(c[2]), "+f"(c[3])
        : "r"(a[0]), "r"(a[1]), "r"(a[2]), "r"(a[3]),
          "r"(b[0]), "r"(b[1]));
}

__device__ __forceinline__ void split2(float x, float y,
                                       uint32_t& hi, uint32_t& lo)
{
    __nv_bfloat162 h = __floats2bfloat162_rn(x, y);
    float hx = __bfloat162float(__low2bfloat16(h));
    float hy = __bfloat162float(__high2bfloat16(h));
    __nv_bfloat162 l = __floats2bfloat162_rn(x - hx, y - hy);
    hi = *(uint32_t*)&h;
    lo = *(uint32_t*)&l;
}

// ---------------------------------------------------------------------------
// Weight transpose + fp32 -> bf16 hi/lo split. B[K][N] -> Bh/Bl[N][K].
// ---------------------------------------------------------------------------
__global__ void transpose_convert_kernel(const float* __restrict__ B,
                                         __nv_bfloat16* __restrict__ Bh,
                                         __nv_bfloat16* __restrict__ Bl,
                                         int K, int N)
{
    __shared__ float t[32][33];
    const int n0 = blockIdx.x * 32;
    const int k0 = blockIdx.y * 32;
    const int x = threadIdx.x, y = threadIdx.y;
#pragma unroll
    for (int i = 0; i < 4; i++)
        t[y + i * 8][x] = B[(size_t)(k0 + y + i * 8) * N + n0 + x];
    __syncthreads();
#pragma unroll
    for (int i = 0; i < 4; i++) {
        float v = t[x][y + i * 8];
        __nv_bfloat16 h = __float2bfloat16(v);
        __nv_bfloat16 l = __float2bfloat16(v - __bfloat162float(h));
        size_t o = (size_t)(n0 + y + i * 8) * K + k0 + x;
        Bh[o] = h;
        Bl[o] = l;
    }
}

// ---------------------------------------------------------------------------
// Split-bf16 tensor-core GEMM via mma.sync.
// C[M,N] = A[M,4096] (fp32) @ W (pre-split Bh/Bl[N][4096] bf16).
// CTA tile 128x128, BK=32, 8 warps (2Mx4N), warp tile 64x32.
// Smem rows stride 80 B (20 words) -> conflict-free fragment lds.
// Double-buffered: prefetch chunk t+1 to regs during compute of chunk t.
// ---------------------------------------------------------------------------
#define WST 80                         // smem row stride in bytes
#define PLANE (128 * WST)              // 10240 B per operand plane
#define SM_TOT (8 * PLANE)             // 4 planes x 2 buffers = 81920 B

__global__ __launch_bounds__(256) void tc_gemm_kernel(
    const float* __restrict__ A,
    const __nv_bfloat16* __restrict__ Bh,
    const __nv_bfloat16* __restrict__ Bl,
    float* __restrict__ C, int N_total)
{
    extern __shared__ char sm[];
    const int tid  = threadIdx.x;
    const int lane = tid & 31;
    const int wid  = tid >> 5;
    const int warpM = wid >> 2;        // 0..1
    const int warpN = wid & 3;         // 0..3
    const int m0 = blockIdx.y * 128;
    const int n0 = blockIdx.x * 128;

    const float* Ag = A + (size_t)m0 * 4096;
    const __nv_bfloat16* Bhg = Bh + (size_t)n0 * 4096;
    const __nv_bfloat16* Blg = Bl + (size_t)n0 * 4096;

    // A staging map: 1024 float4 per chunk (128 rows x 8 f4), 4 per thread
    const int aRow = (tid + 0 * 256) >> 3;   // pattern: i>>3, recomputed below
    (void)aRow;

    float acc[4][4][4];
#pragma unroll
    for (int i = 0; i < 4; i++)
#pragma unroll
        for (int j = 0; j < 4; j++)
#pragma unroll
            for (int c = 0; c < 4; c++) acc[i][j][c] = 0.f;

    float4 pa[4];
    uint4  pb[4];

    auto load_regs = [&](int k0c) {
#pragma unroll
        for (int j = 0; j < 4; j++) {
            int i = tid + j * 256;           // 0..1023
            int row = i >> 3;
            int pos = i & 7;
            pa[j] = *(const float4*)(Ag + (size_t)row * 4096 + k0c + pos * 4);
        }
#pragma unroll
        for (int j = 0; j < 4; j++) {
            int i = tid + j * 256;           // 0..1023
            int plane = i >> 9;              // 0 = hi, 1 = lo
            int r = (i & 511) >> 2;
            int q = i & 3;
            const __nv_bfloat16* src = plane ? Blg : Bhg;
            pb[j] = *(const uint4*)(src + (size_t)r * 4096 + k0c + q * 8);
        }
    };

    auto store_regs = [&](int b) {
        char* ah = sm + (size_t)b * 4 * PLANE;
        char* al = ah + PLANE;
        char* bhp = ah + 2 * PLANE;
        char* blp = ah + 3 * PLANE;
#pragma unroll
        for (int j = 0; j < 4; j++) {
            int i = tid + j * 256;
            int row = i >> 3;
            int pos = i & 7;
            uint32_t h0, l0, h1, l1;
            split2(pa[j].x, pa[j].y, h0, l0);
            split2(pa[j].z, pa[j].w, h1, l1);
            *(uint2*)(ah + row * WST + pos * 8) = make_uint2(h0, h1);
            *(uint2*)(al + row * WST + pos * 8) = make_uint2(l0, l1);
        }
#pragma unroll
        for (int j = 0; j < 4; j++) {
            int i = tid + j * 256;
            int plane = i >> 9;
            int r = (i & 511) >> 2;
            int q = i & 3;
            char* dst = (plane ? blp : bhp) + r * WST + q * 16;
            *(uint4*)dst = pb[j];
        }
    };

    // prologue
    load_regs(0);
    store_regs(0);
    __syncthreads();

#pragma unroll 1
    for (int it = 0; it < 128; ++it) {
        const int b = it & 1;
        const bool hn = (it + 1) < 128;
        if (hn) load_regs((it + 1) * 32);

        const char* ah = sm + (size_t)b * 4 * PLANE;
        const char* al = ah + PLANE;
        const char* bhp = ah + 2 * PLANE;
        const char* blp = ah + 3 * PLANE;

        const int rsel = lane >> 2;          // 0..7
        const int csel = (lane & 3) * 2;     // 0,2,4,6

#pragma unroll
        for (int ks = 0; ks < 2; ++ks) {
            const int kb = ks * 16;          // k base within chunk
            uint32_t fah[4][4], fal[4][4], fbh[4][2], fbl[4][2];
#pragma unroll
            for (int mt = 0; mt < 4; ++mt) {
                int rm = warpM * 64 + mt * 16 + rsel;
                const char* pah = ah + rm * WST + (kb + csel) * 2;
                const char* pal = al + rm * WST + (kb + csel) * 2;
                fah[mt][0] = *(const uint32_t*)(pah);
                fah[mt][1] = *(const uint32_t*)(pah + 8 * WST);
                fah[mt][2] = *(const uint32_t*)(pah + 16);
                fah[mt][3] = *(const uint32_t*)(pah + 8 * WST + 16);
                fal[mt][0] = *(const uint32_t*)(pal);
                fal[mt][1] = *(const uint32_t*)(pal + 8 * WST);
                fal[mt][2] = *(const uint32_t*)(pal + 16);
                fal[mt][3] = *(const uint32_t*)(pal + 8 * WST + 16);
            }
#pragma unroll
            for (int nt = 0; nt < 4; ++nt) {
                int rn = warpN * 32 + nt * 8 + rsel;
                const char* pbh = bhp + rn * WST + (kb + csel) * 2;
                const char* pbl = blp + rn * WST + (kb + csel) * 2;
                fbh[nt][0] = *(const uint32_t*)(pbh);
                fbh[nt][1] = *(const uint32_t*)(pbh + 16);
                fbl[nt][0] = *(const uint32_t*)(pbl);
                fbl[nt][1] = *(const uint32_t*)(pbl + 16);
            }
#pragma unroll
            for (int mt = 0; mt < 4; ++mt)
#pragma unroll
                for (int nt = 0; nt < 4; ++nt) {
                    mma_bf16(acc[mt][nt], fah[mt], fbh[nt]);
                    mma_bf16(acc[mt][nt], fah[mt], fbl[nt]);
                    mma_bf16(acc[mt][nt], fal[mt], fbh[nt]);
                }
        }

        if (hn) store_regs(b ^ 1);
        __syncthreads();
    }

    // epilogue
    const int rsel = lane >> 2;
    const int csel = (lane & 3) * 2;
#pragma unroll
    for (int mt = 0; mt < 4; ++mt) {
#pragma unroll
        for (int nt = 0; nt < 4; ++nt) {
            int row = m0 + warpM * 64 + mt * 16 + rsel;
            int col = n0 + warpN * 32 + nt * 8 + csel;
            *(float2*)(C + (size_t)row * N_total + col) =
                make_float2(acc[mt][nt][0], acc[mt][nt][1]);
            *(float2*)(C + (size_t)(row + 8) * N_total + col) =
                make_float2(acc[mt][nt][2], acc[mt][nt][3]);
        }
    }
}

// ---------------------------------------------------------------------------
// RoPE in-place on q (32 heads) and k (8 heads) inside g_qkv.
// ---------------------------------------------------------------------------
__global__ void rope_kernel(float* __restrict__ qkv,
                            const int* __restrict__ positions)
{
    int idx = blockIdx.x * blockDim.x + threadIdx.x;
    const int total = S_LEN * (NQ + NKV) * 64;
    if (idx >= total) return;
    int j = idx & 63;
    int t = idx >> 6;
    int head = t % (NQ + NKV);
    int s = t / (NQ + NKV);
    int col = (head < NQ) ? head * HD : K_OFF + (head - NQ) * HD;
    float* base = qkv + (size_t)s * QKV_N + col;

    float inv = powf(10000.0f, -((float)j) / 64.0f);
    float ang = (float)positions[s] * inv;
    float sn, cs;
    sincosf(ang, &sn, &cs);
    float x1 = base[j];
    float x2 = base[j + 64];
    base[j]      = x1 * cs - x2 * sn;
    base[j + 64] = x2 * cs + x1 * sn;
}

// ---------------------------------------------------------------------------
// Flash attention, fp32, causal, GQA (unchanged from R9 — passing).
// ---------------------------------------------------------------------------
#define FA_LD 132

struct FaSmem {
    float Qs[64][FA_LD];
    float Ks[64][FA_LD];
    float Vs[64][FA_LD];
    float Ps[64][68];
    int   pq[64];
    int   pk[64];
};

__global__ __launch_bounds__(256) void flash_kernel(
    const float* __restrict__ qkv, const int* __restrict__ positions,
    float* __restrict__ attn)
{
    extern __shared__ char smem_raw[];
    FaSmem& sm = *reinterpret_cast<FaSmem*>(smem_raw);

    const int tid = threadIdx.x;
    const int tx = tid & 15;
    const int ty = tid >> 4;
    const int qb = blockIdx.x * 64;
    const int qh = blockIdx.y;
    const int kvh = qh >> 2;

    {
        const float* qbase = qkv + (size_t)qb * QKV_N + qh * HD;
        for (int i = tid; i < 64 * 32; i += 256) {
            int r = i >> 5, c4 = (i & 31) << 2;
            *(float4*)&sm.Qs[r][c4] = *(const float4*)(qbase + (size_t)r * QKV_N + c4);
        }
        if (tid < 64) sm.pq[tid] = positions[qb + tid];
    }

    float O[4][8];
    float mi[4], li[4];
#pragma unroll
    for (int i = 0; i < 4; i++) {
        mi[i] = -1e30f; li[i] = 0.f;
#pragma unroll
        for (int d = 0; d < 8; d++) O[i][d] = 0.f;
    }

    const int ntiles = (qb >> 6) + 1;
#pragma unroll 1
    for (int t = 0; t < ntiles; t++) {
        const int kb = t * 64;
        __syncthreads();
        {
            const float* kbase = qkv + (size_t)kb * QKV_N + K_OFF + kvh * HD;
            const float* vbase = qkv + (size_t)kb * QKV_N + V_OFF + kvh * HD;
            for (int i = tid; i < 64 * 32; i += 256) {
                int r = i >> 5, c4 = (i & 31) << 2;
                *(float4*)&sm.Ks[r][c4] = *(const float4*)(kbase + (size_t)r * QKV_N + c4);
                *(float4*)&sm.Vs[r][c4] = *(const float4*)(vbase + (size_t)r * QKV_N + c4);
            }
            if (tid < 64) sm.pk[tid] = positions[kb + tid];
        }
        __syncthreads();

        float s[4][4];
#pragma unroll
        for (int i = 0; i < 4; i++)
#pragma unroll
            for (int j = 0; j < 4; j++) s[i][j] = 0.f;

#pragma unroll 4
        for (int k4 = 0; k4 < 32; k4++) {
            float4 q[4], k[4];
#pragma unroll
            for (int i = 0; i < 4; i++) q[i] = *(const float4*)&sm.Qs[ty * 4 + i][k4 * 4];
#pragma unroll
            for (int j = 0; j < 4; j++) k[j] = *(const float4*)&sm.Ks[tx * 4 + j][k4 * 4];
#pragma unroll
            for (int i = 0; i < 4; i++)
#pragma unroll
                for (int j = 0; j < 4; j++) {
                    s[i][j] = fmaf(q[i].x, k[j].x, s[i][j]);
                    s[i][j] = fmaf(q[i].y, k[j].y, s[i][j]);
                    s[i][j] = fmaf(q[i].z, k[j].z, s[i][j]);
                    s[i][j] = fmaf(q[i].w, k[j].w, s[i][j]);
                }
        }

#pragma unroll
        for (int i = 0; i < 4; i++) {
            const int prow = sm.pq[ty * 4 + i];
            float m = -1e30f;
#pragma unroll
            for (int j = 0; j < 4; j++) {
                bool ok = (sm.pk[tx * 4 + j] <= prow);
                s[i][j] = ok ? s[i][j] * SCALE_F : -1e30f;
                m = fmaxf(m, s[i][j]);
            }
#pragma unroll
            for (int off = 8; off > 0; off >>= 1)
                m = fmaxf(m, __shfl_xor_sync(0xffffffffu, m, off));

            float mn = fmaxf(mi[i], m);
            float corr = __expf(mi[i] - mn);
            mi[i] = mn;

            float rs = 0.f;
#pragma unroll
            for (int j = 0; j < 4; j++) {
                float p = __expf(s[i][j] - mn);
                sm.Ps[ty * 4 + i][tx * 4 + j] = p;
                rs += p;
            }
#pragma unroll
            for (int off = 8; off > 0; off >>= 1)
                rs += __shfl_xor_sync(0xffffffffu, rs, off);

            li[i] = li[i] * corr + rs;
#pragma unroll
            for (int d = 0; d < 8; d++) O[i][d] *= corr;
        }
        __syncthreads();

#pragma unroll 4
        for (int c = 0; c < 64; c++) {
            float4 v0 = *(const float4*)&sm.Vs[c][tx * 8];
            float4 v1 = *(const float4*)&sm.Vs[c][tx * 8 + 4];
#pragma unroll
            for (int i = 0; i < 4; i++) {
                float p = sm.Ps[ty * 4 + i][c];
                O[i][0] = fmaf(p, v0.x, O[i][0]);
                O[i][1] = fmaf(p, v0.y, O[i][1]);
                O[i][2] = fmaf(p, v0.z, O[i][2]);
                O[i][3] = fmaf(p, v0.w, O[i][3]);
                O[i][4] = fmaf(p, v1.x, O[i][4]);
                O[i][5] = fmaf(p, v1.y, O[i][5]);
                O[i][6] = fmaf(p, v1.z, O[i][6]);
                O[i][7] = fmaf(p, v1.w, O[i][7]);
            }
        }
    }

#pragma unroll
    for (int i = 0; i < 4; i++) {
        float inv = 1.0f / li[i];
        float* dst = attn + (size_t)(qb + ty * 4 + i) * HID + qh * HD + tx * 8;
        float4 o0 = make_float4(O[i][0] * inv, O[i][1] * inv, O[i][2] * inv, O[i][3] * inv);
        float4 o1 = make_float4(O[i][4] * inv, O[i][5] * inv, O[i][6] * inv, O[i][7] * inv);
        *(float4*)dst       = o0;
        *(float4*)(dst + 4) = o1;
    }
}

// ---------------------------------------------------------------------------
// launch
// ---------------------------------------------------------------------------
extern "C" void kernel_launch(void* const* d_in, const int* in_sizes, int n_in,
                              void* d_out, int out_size)
{
    const int*   positions = (const int*)d_in[0];
    const float* hidden    = (const float*)d_in[1];
    const float* w_qkv     = (const float*)d_in[2];
    const float* w_o       = (const float*)d_in[3];
    float*       out       = (float*)d_out;

    float *qkv = nullptr, *attn = nullptr;
    __nv_bfloat16 *bhq = nullptr, *blq = nullptr, *bho = nullptr, *blo = nullptr;
    cudaGetSymbolAddress((void**)&qkv,  g_qkv);
    cudaGetSymbolAddress((void**)&attn, g_attn);
    cudaGetSymbolAddress((void**)&bhq,  g_bh_qkv);
    cudaGetSymbolAddress((void**)&blq,  g_bl_qkv);
    cudaGetSymbolAddress((void**)&bho,  g_bh_o);
    cudaGetSymbolAddress((void**)&blo,  g_bl_o);

    // 0) transpose + split-convert both weight matrices
    transpose_convert_kernel<<<dim3(QKV_N / 32, HID / 32), dim3(32, 8)>>>(
        w_qkv, bhq, blq, HID, QKV_N);
    transpose_convert_kernel<<<dim3(HID / 32, HID / 32), dim3(32, 8)>>>(
        w_o, bho, blo, HID, HID);

    cudaFuncSetAttribute(tc_gemm_kernel,
                         cudaFuncAttributeMaxDynamicSharedMemorySize, SM_TOT);

    // 1) QKV projection (mma.sync split-bf16)
    tc_gemm_kernel<<<dim3(QKV_N / 128, S_LEN / 128), 256, SM_TOT>>>(
        hidden, bhq, blq, qkv, QKV_N);

    // 2) RoPE
    {
        int total = S_LEN * (NQ + NKV) * 64;
        rope_kernel<<<(total + 255) / 256, 256>>>(qkv, positions);
    }

    // 3) Flash attention (fp32)
    {
        size_t smem = sizeof(FaSmem);
        cudaFuncSetAttribute(flash_kernel,
                             cudaFuncAttributeMaxDynamicSharedMemorySize,
                             (int)smem);
        flash_kernel<<<dim3(S_LEN / 64, NQ), 256, smem>>>(qkv, positions, attn);
    }

    // 4) Output projection (mma.sync split-bf16)
    tc_gemm_kernel<<<dim3(HID / 128, S_LEN / 128), 256, SM_TOT>>>(
        attn, bho, blo, out, HID);
}

// round 12
// speedup vs baseline: 2.7309x; 2.0033x over previous
#include <cuda_runtime.h>
#include <cuda_bf16.h>
#include <cuda_fp16.h>
#include <cstdint>
#include <cstddef>

// Problem constants
#define S_LEN 4096
#define HID   4096
#define NQ    32
#define NKV   8
#define HD    128
#define QKV_N 6144              // NQ*HD + 2*NKV*HD
#define K_OFF 4096              // NQ*HD
#define V_OFF 5120              // NQ*HD + NKV*HD
#define SCALE_F 0.08838834764831843f   // 128^-0.5

// Scratch (allocations forbidden -> device globals)
__device__ float g_qkv[(size_t)S_LEN * QKV_N];   // ~100.7 MB
__device__ float g_attn[(size_t)S_LEN * HID];    // ~67 MB
// bf16 hi/lo transposed weights: [N][K] layout, K = 4096
__device__ __nv_bfloat16 g_bh_qkv[(size_t)QKV_N * HID];
__device__ __nv_bfloat16 g_bl_qkv[(size_t)QKV_N * HID];
__device__ __nv_bfloat16 g_bh_o[(size_t)HID * HID];
__device__ __nv_bfloat16 g_bl_o[(size_t)HID * HID];

// ---------------------------------------------------------------------------
// mma.sync helpers (arch-agnostic tensor path; valid on plain sm_103 target)
// ---------------------------------------------------------------------------
__device__ __forceinline__ void mma_bf16(float* c, const uint32_t* a,
                                         const uint32_t* b)
{
    asm volatile(
        "mma.sync.aligned.m16n8k16.row.col.f32.bf16.bf16.f32 "
        "{%0,%1,%2,%3}, {%4,%5,%6,%7}, {%8,%9}, {%0,%1,%2,%3};\n"
        : "+f"(c[0]), "+f"(c[1]), "+f"(c[2]), "+f"(c[3])
        : "r"(a[0]), "r"(a[1]), "r"(a[2]), "r"(a[3]),
          "r"(b[0]), "r"(b[1]));
}

__device__ __forceinline__ void mma_f16(float* c, const uint32_t* a,
                                        const uint32_t* b)
{
    asm volatile(
        "mma.sync.aligned.m16n8k16.row.col.f32.f16.f16.f32 "
        "{%0,%1,%2,%3}, {%4,%5,%6,%7}, {%8,%9}, {%0,%1,%2,%3};\n"
        : "+f"(c[0]), "+f"(c[1]), "+f"(c[2]), "+f"(c[3])
        : "r"(a[0]), "r"(a[1]), "r"(a[2]), "r"(a[3]),
          "r"(b[0]), "r"(b[1]));
}

__device__ __forceinline__ void split2(float x, float y,
                                       uint32_t& hi, uint32_t& lo)
{
    __nv_bfloat162 h = __floats2bfloat162_rn(x, y);
    float hx = __bfloat162float(__low2bfloat16(h));
    float hy = __bfloat162float(__high2bfloat16(h));
    __nv_bfloat162 l = __floats2bfloat162_rn(x - hx, y - hy);
    hi = *(uint32_t*)&h;
    lo = *(uint32_t*)&l;
}

__device__ __forceinline__ uint32_t packh2(__half a, __half b) {
    __half2 h = __halves2half2(a, b);
    return *(uint32_t*)&h;
}

__device__ __forceinline__ void splith(float x, __half& h, __half& l) {
    h = __float2half(x);
    l = __float2half(x - __half2float(h));
}

// ---------------------------------------------------------------------------
// Weight transpose + fp32 -> bf16 hi/lo split. B[K][N] -> Bh/Bl[N][K].
// ---------------------------------------------------------------------------
__global__ void transpose_convert_kernel(const float* __restrict__ B,
                                         __nv_bfloat16* __restrict__ Bh,
                                         __nv_bfloat16* __restrict__ Bl,
                                         int K, int N)
{
    __shared__ float t[32][33];
    const int n0 = blockIdx.x * 32;
    const int k0 = blockIdx.y * 32;
    const int x = threadIdx.x, y = threadIdx.y;
#pragma unroll
    for (int i = 0; i < 4; i++)
        t[y + i * 8][x] = B[(size_t)(k0 + y + i * 8) * N + n0 + x];
    __syncthreads();
#pragma unroll
    for (int i = 0; i < 4; i++) {
        float v = t[x][y + i * 8];
        __nv_bfloat16 h = __float2bfloat16(v);
        __nv_bfloat16 l = __float2bfloat16(v - __bfloat162float(h));
        size_t o = (size_t)(n0 + y + i * 8) * K + k0 + x;
        Bh[o] = h;
        Bl[o] = l;
    }
}

// ---------------------------------------------------------------------------
// Split-bf16 tensor-core GEMM via mma.sync (unchanged from R11 — validated).
// ---------------------------------------------------------------------------
#define WST 80
#define PLANE (128 * WST)
#define SM_TOT (8 * PLANE)

__global__ __launch_bounds__(256) void tc_gemm_kernel(
    const float* __restrict__ A,
    const __nv_bfloat16* __restrict__ Bh,
    const __nv_bfloat16* __restrict__ Bl,
    float* __restrict__ C, int N_total)
{
    extern __shared__ char sm[];
    const int tid  = threadIdx.x;
    const int lane = tid & 31;
    const int wid  = tid >> 5;
    const int warpM = wid >> 2;
    const int warpN = wid & 3;
    const int m0 = blockIdx.y * 128;
    const int n0 = blockIdx.x * 128;

    const float* Ag = A + (size_t)m0 * 4096;
    const __nv_bfloat16* Bhg = Bh + (size_t)n0 * 4096;
    const __nv_bfloat16* Blg = Bl + (size_t)n0 * 4096;

    float acc[4][4][4];
#pragma unroll
    for (int i = 0; i < 4; i++)
#pragma unroll
        for (int j = 0; j < 4; j++)
#pragma unroll
            for (int c = 0; c < 4; c++) acc[i][j][c] = 0.f;

    float4 pa[4];
    uint4  pb[4];

    auto load_regs = [&](int k0c) {
#pragma unroll
        for (int j = 0; j < 4; j++) {
            int i = tid + j * 256;
            int row = i >> 3;
            int pos = i & 7;
            pa[j] = *(const float4*)(Ag + (size_t)row * 4096 + k0c + pos * 4);
        }
#pragma unroll
        for (int j = 0; j < 4; j++) {
            int i = tid + j * 256;
            int plane = i >> 9;
            int r = (i & 511) >> 2;
            int q = i & 3;
            const __nv_bfloat16* src = plane ? Blg : Bhg;
            pb[j] = *(const uint4*)(src + (size_t)r * 4096 + k0c + q * 8);
        }
    };

    auto store_regs = [&](int b) {
        char* ah = sm + (size_t)b * 4 * PLANE;
        char* al = ah + PLANE;
        char* bhp = ah + 2 * PLANE;
        char* blp = ah + 3 * PLANE;
#pragma unroll
        for (int j = 0; j < 4; j++) {
            int i = tid + j * 256;
            int row = i >> 3;
            int pos = i & 7;
            uint32_t h0, l0, h1, l1;
            split2(pa[j].x, pa[j].y, h0, l0);
            split2(pa[j].z, pa[j].w, h1, l1);
            *(uint2*)(ah + row * WST + pos * 8) = make_uint2(h0, h1);
            *(uint2*)(al + row * WST + pos * 8) = make_uint2(l0, l1);
        }
#pragma unroll
        for (int j = 0; j < 4; j++) {
            int i = tid + j * 256;
            int plane = i >> 9;
            int r = (i & 511) >> 2;
            int q = i & 3;
            char* dst = (plane ? blp : bhp) + r * WST + q * 16;
            *(uint4*)dst = pb[j];
        }
    };

    load_regs(0);
    store_regs(0);
    __syncthreads();

#pragma unroll 1
    for (int it = 0; it < 128; ++it) {
        const int b = it & 1;
        const bool hn = (it + 1) < 128;
        if (hn) load_regs((it + 1) * 32);

        const char* ah = sm + (size_t)b * 4 * PLANE;
        const char* al = ah + PLANE;
        const char* bhp = ah + 2 * PLANE;
        const char* blp = ah + 3 * PLANE;

        const int rsel = lane >> 2;
        const int csel = (lane & 3) * 2;

#pragma unroll
        for (int ks = 0; ks < 2; ++ks) {
            const int kb = ks * 16;
            uint32_t fah[4][4], fal[4][4], fbh[4][2], fbl[4][2];
#pragma unroll
            for (int mt = 0; mt < 4; ++mt) {
                int rm = warpM * 64 + mt * 16 + rsel;
                const char* pah = ah + rm * WST + (kb + csel) * 2;
                const char* pal = al + rm * WST + (kb + csel) * 2;
                fah[mt][0] = *(const uint32_t*)(pah);
                fah[mt][1] = *(const uint32_t*)(pah + 8 * WST);
                fah[mt][2] = *(const uint32_t*)(pah + 16);
                fah[mt][3] = *(const uint32_t*)(pah + 8 * WST + 16);
                fal[mt][0] = *(const uint32_t*)(pal);
                fal[mt][1] = *(const uint32_t*)(pal + 8 * WST);
                fal[mt][2] = *(const uint32_t*)(pal + 16);
                fal[mt][3] = *(const uint32_t*)(pal + 8 * WST + 16);
            }
#pragma unroll
            for (int nt = 0; nt < 4; ++nt) {
                int rn = warpN * 32 + nt * 8 + rsel;
                const char* pbh = bhp + rn * WST + (kb + csel) * 2;
                const char* pbl = blp + rn * WST + (kb + csel) * 2;
                fbh[nt][0] = *(const uint32_t*)(pbh);
                fbh[nt][1] = *(const uint32_t*)(pbh + 16);
                fbl[nt][0] = *(const uint32_t*)(pbl);
                fbl[nt][1] = *(const uint32_t*)(pbl + 16);
            }
#pragma unroll
            for (int mt = 0; mt < 4; ++mt)
#pragma unroll
                for (int nt = 0; nt < 4; ++nt) {
                    mma_bf16(acc[mt][nt], fah[mt], fbh[nt]);
                    mma_bf16(acc[mt][nt], fah[mt], fbl[nt]);
                    mma_bf16(acc[mt][nt], fal[mt], fbh[nt]);
                }
        }

        if (hn) store_regs(b ^ 1);
        __syncthreads();
    }

    const int rsel = lane >> 2;
    const int csel = (lane & 3) * 2;
#pragma unroll
    for (int mt = 0; mt < 4; ++mt) {
#pragma unroll
        for (int nt = 0; nt < 4; ++nt) {
            int row = m0 + warpM * 64 + mt * 16 + rsel;
            int col = n0 + warpN * 32 + nt * 8 + csel;
            *(float2*)(C + (size_t)row * N_total + col) =
                make_float2(acc[mt][nt][0], acc[mt][nt][1]);
            *(float2*)(C + (size_t)(row + 8) * N_total + col) =
                make_float2(acc[mt][nt][2], acc[mt][nt][3]);
        }
    }
}

// ---------------------------------------------------------------------------
// RoPE in-place on q (32 heads) and k (8 heads) inside g_qkv.
// ---------------------------------------------------------------------------
__global__ void rope_kernel(float* __restrict__ qkv,
                            const int* __restrict__ positions)
{
    int idx = blockIdx.x * blockDim.x + threadIdx.x;
    const int total = S_LEN * (NQ + NKV) * 64;
    if (idx >= total) return;
    int j = idx & 63;
    int t = idx >> 6;
    int head = t % (NQ + NKV);
    int s = t / (NQ + NKV);
    int col = (head < NQ) ? head * HD : K_OFF + (head - NQ) * HD;
    float* base = qkv + (size_t)s * QKV_N + col;

    float inv = powf(10000.0f, -((float)j) / 64.0f);
    float ang = (float)positions[s] * inv;
    float sn, cs;
    sincosf(ang, &sn, &cs);
    float x1 = base[j];
    float x2 = base[j + 64];
    base[j]      = x1 * cs - x2 * sn;
    base[j + 64] = x2 * cs + x1 * sn;
}

// ---------------------------------------------------------------------------
// Flash attention via mma.sync fp16.
// Grid (64, 32): x = q-tile (reversed for tail balance), y = q-head.
// 128 threads = 4 warps; warp w owns q rows [w*16, w*16+16).
// QK: fp16 unsplit (score error negligible). PV: P and V hi/lo split fp16.
// Causal mask applied on diagonal tile only (positions are arange).
// ---------------------------------------------------------------------------
#define FQ_ST 272                 // Q/K smem row stride (128 fp16 + 16B pad)
#define FV_ST 144                 // Vt smem row stride (64 fp16 + 16B pad)
#define FLS_Q  0
#define FLS_K  (64 * FQ_ST)                 // 17408
#define FLS_VH (FLS_K + 64 * FQ_ST)         // 34816
#define FLS_VL (FLS_VH + 128 * FV_ST)       // 53248
#define FLS_TOT (FLS_VL + 128 * FV_ST)      // 71680

__global__ __launch_bounds__(128) void flash_mma_kernel(
    const float* __restrict__ qkv, float* __restrict__ attn)
{
    extern __shared__ char fsm[];
    char* Qs = fsm + FLS_Q;
    char* Ks = fsm + FLS_K;
    char* Vh = fsm + FLS_VH;
    char* Vl = fsm + FLS_VL;

    const int tid  = threadIdx.x;
    const int lane = tid & 31;
    const int wid  = tid >> 5;
    const int qb = (gridDim.x - 1 - blockIdx.x) * 64;
    const int qh = blockIdx.y;
    const int kvh = qh >> 2;

    const int rsel = lane >> 2;          // 0..7
    const int cs4  = (lane & 3) * 4;     // byte offset of element 2*(lane&3)

    // Load Q tile [64][128], scale folded, fp32 -> fp16
    {
        const float* qbase = qkv + (size_t)qb * QKV_N + qh * HD;
        for (int i = tid; i < 64 * 64; i += 128) {
            int r = i >> 6, c2 = i & 63;
            float2 v = *(const float2*)(qbase + (size_t)r * QKV_N + c2 * 2);
            __half2 h = __floats2half2_rn(v.x * SCALE_F, v.y * SCALE_F);
            *(uint32_t*)(Qs + r * FQ_ST + c2 * 4) = *(uint32_t*)&h;
        }
    }

    float Of[16][4];
#pragma unroll
    for (int nt = 0; nt < 16; ++nt)
#pragma unroll
        for (int c = 0; c < 4; ++c) Of[nt][c] = 0.f;
    float mi0 = -1e30f, mi1 = -1e30f, li0 = 0.f, li1 = 0.f;

    const int ntiles = (qb >> 6) + 1;
#pragma unroll 1
    for (int t = 0; t < ntiles; ++t) {
        const int kb = t * 64;
        __syncthreads();   // consumers of previous K/V (and Q store) done
        {
            const float* kbase = qkv + (size_t)kb * QKV_N + K_OFF + kvh * HD;
            const float* vbase = qkv + (size_t)kb * QKV_N + V_OFF + kvh * HD;
            for (int i = tid; i < 64 * 64; i += 128) {
                int r = i >> 6, c2 = i & 63;
                float2 kv2 = *(const float2*)(kbase + (size_t)r * QKV_N + c2 * 2);
                __half2 kh = __floats2half2_rn(kv2.x, kv2.y);
                *(uint32_t*)(Ks + r * FQ_ST + c2 * 4) = *(uint32_t*)&kh;

                float2 vv = *(const float2*)(vbase + (size_t)r * QKV_N + c2 * 2);
                __half h0, l0, h1, l1;
                splith(vv.x, h0, l0);
                splith(vv.y, h1, l1);
                int d0 = c2 * 2;
                *(__half*)(Vh + (d0 + 0) * FV_ST + r * 2) = h0;
                *(__half*)(Vh + (d0 + 1) * FV_ST + r * 2) = h1;
                *(__half*)(Vl + (d0 + 0) * FV_ST + r * 2) = l0;
                *(__half*)(Vl + (d0 + 1) * FV_ST + r * 2) = l1;
            }
        }
        __syncthreads();

        // ---- S = Q K^T (warp tile m16 x n64) ----
        float s[8][4];
#pragma unroll
        for (int j = 0; j < 8; ++j)
#pragma unroll
            for (int c = 0; c < 4; ++c) s[j][c] = 0.f;

#pragma unroll
        for (int kk = 0; kk < 8; ++kk) {
            uint32_t a[4];
            const char* pa = Qs + (wid * 16 + rsel) * FQ_ST + kk * 32 + cs4;
            a[0] = *(const uint32_t*)(pa);
            a[1] = *(const uint32_t*)(pa + 8 * FQ_ST);
            a[2] = *(const uint32_t*)(pa + 16);
            a[3] = *(const uint32_t*)(pa + 8 * FQ_ST + 16);
#pragma unroll
            for (int j = 0; j < 8; ++j) {
                uint32_t b[2];
                const char* pb = Ks + (j * 8 + rsel) * FQ_ST + kk * 32 + cs4;
                b[0] = *(const uint32_t*)(pb);
                b[1] = *(const uint32_t*)(pb + 16);
                mma_f16(s[j], a, b);
            }
        }

        // ---- causal mask: only the diagonal tile needs it ----
        if (t == ntiles - 1) {
            const int rl0 = wid * 16 + rsel;
            const int rl1 = rl0 + 8;
#pragma unroll
            for (int j = 0; j < 8; ++j) {
                int c0 = j * 8 + (lane & 3) * 2;
                int c1 = c0 + 1;
                if (c0 > rl0) s[j][0] = -1e30f;
                if (c1 > rl0) s[j][1] = -1e30f;
                if (c0 > rl1) s[j][2] = -1e30f;
                if (c1 > rl1) s[j][3] = -1e30f;
            }
        }

        // ---- online softmax (rows live in quads) ----
        float m0 = -1e30f, m1 = -1e30f;
#pragma unroll
        for (int j = 0; j < 8; ++j) {
            m0 = fmaxf(m0, fmaxf(s[j][0], s[j][1]));
            m1 = fmaxf(m1, fmaxf(s[j][2], s[j][3]));
        }
        m0 = fmaxf(m0, __shfl_xor_sync(0xffffffffu, m0, 1));
        m0 = fmaxf(m0, __shfl_xor_sync(0xffffffffu, m0, 2));
        m1 = fmaxf(m1, __shfl_xor_sync(0xffffffffu, m1, 1));
        m1 = fmaxf(m1, __shfl_xor_sync(0xffffffffu, m1, 2));

        float mn0 = fmaxf(mi0, m0);
        float mn1 = fmaxf(mi1, m1);
        float corr0 = __expf(mi0 - mn0);
        float corr1 = __expf(mi1 - mn1);
        mi0 = mn0; mi1 = mn1;

        uint32_t ph[4][4], pl[4][4];
        float rs0 = 0.f, rs1 = 0.f;
#pragma unroll
        for (int j = 0; j < 8; ++j) {
            float p0 = __expf(s[j][0] - mn0);
            float p1 = __expf(s[j][1] - mn0);
            float p2 = __expf(s[j][2] - mn1);
            float p3 = __expf(s[j][3] - mn1);
            rs0 += p0 + p1;
            rs1 += p2 + p3;
            __half h0, l0, h1, l1, h2, l2, h3, l3;
            splith(p0, h0, l0); splith(p1, h1, l1);
            splith(p2, h2, l2); splith(p3, h3, l3);
            int kk = j >> 1, w = (j & 1) * 2;
            ph[kk][w + 0] = packh2(h0, h1);
            ph[kk][w + 1] = packh2(h2, h3);
            pl[kk][w + 0] = packh2(l0, l1);
            pl[kk][w + 1] = packh2(l2, l3);
        }
        rs0 += __shfl_xor_sync(0xffffffffu, rs0, 1);
        rs0 += __shfl_xor_sync(0xffffffffu, rs0, 2);
        rs1 += __shfl_xor_sync(0xffffffffu, rs1, 1);
        rs1 += __shfl_xor_sync(0xffffffffu, rs1, 2);
        li0 = li0 * corr0 + rs0;
        li1 = li1 * corr1 + rs1;

#pragma unroll
        for (int nt = 0; nt < 16; ++nt) {
            Of[nt][0] *= corr0; Of[nt][1] *= corr0;
            Of[nt][2] *= corr1; Of[nt][3] *= corr1;
        }

        // ---- O += P @ V (Ph*Vh + Pl*Vh + Ph*Vl) ----
#pragma unroll
        for (int kk = 0; kk < 4; ++kk) {
#pragma unroll
            for (int nt = 0; nt < 16; ++nt) {
                const char* pbh = Vh + (nt * 8 + rsel) * FV_ST + kk * 32 + cs4;
                const char* pbl = Vl + (nt * 8 + rsel) * FV_ST + kk * 32 + cs4;
                uint32_t bh[2], bl[2];
                bh[0] = *(const uint32_t*)(pbh);
                bh[1] = *(const uint32_t*)(pbh + 16);
                bl[0] = *(const uint32_t*)(pbl);
                bl[1] = *(const uint32_t*)(pbl + 16);
                mma_f16(Of[nt], ph[kk], bh);
                mma_f16(Of[nt], pl[kk], bh);
                mma_f16(Of[nt], ph[kk], bl);
            }
        }
    }

    // ---- epilogue ----
    const float inv0 = 1.0f / li0;
    const float inv1 = 1.0f / li1;
    const int row0 = qb + wid * 16 + rsel;
    const int row1 = row0 + 8;
#pragma unroll
    for (int nt = 0; nt < 16; ++nt) {
        int col = qh * HD + nt * 8 + (lane & 3) * 2;
        *(float2*)(attn + (size_t)row0 * HID + col) =
            make_float2(Of[nt][0] * inv0, Of[nt][1] * inv0);
        *(float2*)(attn + (size_t)row1 * HID + col) =
            make_float2(Of[nt][2] * inv1, Of[nt][3] * inv1);
    }
}

// ---------------------------------------------------------------------------
// launch
// ---------------------------------------------------------------------------
extern "C" void kernel_launch(void* const* d_in, const int* in_sizes, int n_in,
                              void* d_out, int out_size)
{
    const int*   positions = (const int*)d_in[0];
    const float* hidden    = (const float*)d_in[1];
    const float* w_qkv     = (const float*)d_in[2];
    const float* w_o       = (const float*)d_in[3];
    float*       out       = (float*)d_out;

    float *qkv = nullptr, *attn = nullptr;
    __nv_bfloat16 *bhq = nullptr, *blq = nullptr, *bho = nullptr, *blo = nullptr;
    cudaGetSymbolAddress((void**)&qkv,  g_qkv);
    cudaGetSymbolAddress((void**)&attn, g_attn);
    cudaGetSymbolAddress((void**)&bhq,  g_bh_qkv);
    cudaGetSymbolAddress((void**)&blq,  g_bl_qkv);
    cudaGetSymbolAddress((void**)&bho,  g_bh_o);
    cudaGetSymbolAddress((void**)&blo,  g_bl_o);

    // 0) transpose + split-convert both weight matrices
    transpose_convert_kernel<<<dim3(QKV_N / 32, HID / 32), dim3(32, 8)>>>(
        w_qkv, bhq, blq, HID, QKV_N);
    transpose_convert_kernel<<<dim3(HID / 32, HID / 32), dim3(32, 8)>>>(
        w_o, bho, blo, HID, HID);

    cudaFuncSetAttribute(tc_gemm_kernel,
                         cudaFuncAttributeMaxDynamicSharedMemorySize, SM_TOT);

    // 1) QKV projection (mma.sync split-bf16)
    tc_gemm_kernel<<<dim3(QKV_N / 128, S_LEN / 128), 256, SM_TOT>>>(
        hidden, bhq, blq, qkv, QKV_N);

    // 2) RoPE
    {
        int total = S_LEN * (NQ + NKV) * 64;
        rope_kernel<<<(total + 255) / 256, 256>>>(qkv, positions);
    }

    // 3) Flash attention (mma.sync fp16, split P/V)
    {
        cudaFuncSetAttribute(flash_mma_kernel,
                             cudaFuncAttributeMaxDynamicSharedMemorySize,
                             FLS_TOT);
        flash_mma_kernel<<<dim3(S_LEN / 64, NQ), 128, FLS_TOT>>>(qkv, attn);
    }

    // 4) Output projection (mma.sync split-bf16)
    tc_gemm_kernel<<<dim3(HID / 128, S_LEN / 128), 256, SM_TOT>>>(
        attn, bho, blo, out, HID);
}

// round 15
// speedup vs baseline: 2.9967x; 1.0973x over previous
#include <cuda_runtime.h>
#include <cuda_bf16.h>
#include <cuda_fp16.h>
#include <cstdint>
#include <cstddef>

// Problem constants
#define S_LEN 4096
#define HID   4096
#define NQ    32
#define NKV   8
#define HD    128
#define QKV_N 6144              // NQ*HD + 2*NKV*HD
#define K_OFF 4096              // NQ*HD
#define V_OFF 5120              // NQ*HD + NKV*HD
#define SCALE_F 0.08838834764831843f   // 128^-0.5

// Scratch (allocations forbidden -> device globals)
__device__ float g_qkv[(size_t)S_LEN * QKV_N];   // ~100.7 MB
// hi/lo bf16 split planes of GEMM A operands
__device__ __nv_bfloat16 g_hid_h[(size_t)S_LEN * HID];
__device__ __nv_bfloat16 g_hid_l[(size_t)S_LEN * HID];
__device__ __nv_bfloat16 g_at_h[(size_t)S_LEN * HID];
__device__ __nv_bfloat16 g_at_l[(size_t)S_LEN * HID];
// bf16 hi/lo transposed weights: [N][K] layout, K = 4096
__device__ __nv_bfloat16 g_bh_qkv[(size_t)QKV_N * HID];
__device__ __nv_bfloat16 g_bl_qkv[(size_t)QKV_N * HID];
__device__ __nv_bfloat16 g_bh_o[(size_t)HID * HID];
__device__ __nv_bfloat16 g_bl_o[(size_t)HID * HID];

// ---------------------------------------------------------------------------
// mma.sync helpers (arch-agnostic tensor path; valid on plain sm_103 target)
// ---------------------------------------------------------------------------
__device__ __forceinline__ void mma_bf16(float* c, const uint32_t* a,
                                         const uint32_t* b)
{
    asm volatile(
        "mma.sync.aligned.m16n8k16.row.col.f32.bf16.bf16.f32 "
        "{%0,%1,%2,%3}, {%4,%5,%6,%7}, {%8,%9}, {%0,%1,%2,%3};\n"
        : "+f"(c[0]), "+f"(c[1]), "+f"(c[2]), "+f"(c[3])
        : "r"(a[0]), "r"(a[1]), "r"(a[2]), "r"(a[3]),
          "r"(b[0]), "r"(b[1]));
}

__device__ __forceinline__ void mma_f16(float* c, const uint32_t* a,
                                        const uint32_t* b)
{
    asm volatile(
        "mma.sync.aligned.m16n8k16.row.col.f32.f16.f16.f32 "
        "{%0,%1,%2,%3}, {%4,%5,%6,%7}, {%8,%9}, {%0,%1,%2,%3};\n"
        : "+f"(c[0]), "+f"(c[1]), "+f"(c[2]), "+f"(c[3])
        : "r"(a[0]), "r"(a[1]), "r"(a[2]), "r"(a[3]),
          "r"(b[0]), "r"(b[1]));
}

__device__ __forceinline__ void split2(float x, float y,
                                       uint32_t& hi, uint32_t& lo)
{
    __nv_bfloat162 h = __floats2bfloat162_rn(x, y);
    float hx = __bfloat162float(__low2bfloat16(h));
    float hy = __bfloat162float(__high2bfloat16(h));
    __nv_bfloat162 l = __floats2bfloat162_rn(x - hx, y - hy);
    hi = *(uint32_t*)&h;
    lo = *(uint32_t*)&l;
}

__device__ __forceinline__ uint32_t packh2(__half a, __half b) {
    __half2 h = __halves2half2(a, b);
    return *(uint32_t*)&h;
}

__device__ __forceinline__ void splith(float x, __half& h, __half& l) {
    h = __float2half(x);
    l = __float2half(x - __half2float(h));
}

// ---------------------------------------------------------------------------
// Weight transpose + fp32 -> bf16 hi/lo split. B[K][N] -> Bh/Bl[N][K].
// ---------------------------------------------------------------------------
__global__ void transpose_convert_kernel(const float* __restrict__ B,
                                         __nv_bfloat16* __restrict__ Bh,
                                         __nv_bfloat16* __restrict__ Bl,
                                         int K, int N)
{
    __shared__ float t[32][33];
    const int n0 = blockIdx.x * 32;
    const int k0 = blockIdx.y * 32;
    const int x = threadIdx.x, y = threadIdx.y;
#pragma unroll
    for (int i = 0; i < 4; i++)
        t[y + i * 8][x] = B[(size_t)(k0 + y + i * 8) * N + n0 + x];
    __syncthreads();
#pragma unroll
    for (int i = 0; i < 4; i++) {
        float v = t[x][y + i * 8];
        __nv_bfloat16 h = __float2bfloat16(v);
        __nv_bfloat16 l = __float2bfloat16(v - __bfloat162float(h));
        size_t o = (size_t)(n0 + y + i * 8) * K + k0 + x;
        Bh[o] = h;
        Bl[o] = l;
    }
}

// ---------------------------------------------------------------------------
// Elementwise fp32 -> bf16 hi/lo split (for the QKV GEMM's A = hidden).
// ---------------------------------------------------------------------------
__global__ void split_a_kernel(const float* __restrict__ A,
                               __nv_bfloat16* __restrict__ Ah,
                               __nv_bfloat16* __restrict__ Al)
{
    int i = blockIdx.x * blockDim.x + threadIdx.x;   // per float2
    const int total2 = S_LEN * HID / 2;
    if (i >= total2) return;
    float2 v = *(const float2*)(A + (size_t)i * 2);
    uint32_t h, l;
    split2(v.x, v.y, h, l);
    ((uint32_t*)Ah)[i] = h;
    ((uint32_t*)Al)[i] = l;
}

// ---------------------------------------------------------------------------
// Split-bf16 tensor-core GEMM via mma.sync.
// C[M,N] = (Ah+Al)[M,4096] @ (Bh+Bl)[N,4096]^T, all operands pre-split bf16.
// CTA tile 128x128, BK=32, 8 warps (2Mx4N), warp tile 64x32.
// Staging is pure uint4 copies (no conversion in the hot loop).
// ---------------------------------------------------------------------------
#define WST 80
#define PLANE (128 * WST)
#define SM_TOT (8 * PLANE)

__global__ __launch_bounds__(256) void tc_gemm_kernel(
    const __nv_bfloat16* __restrict__ Ah,
    const __nv_bfloat16* __restrict__ Al,
    const __nv_bfloat16* __restrict__ Bh,
    const __nv_bfloat16* __restrict__ Bl,
    float* __restrict__ C, int N_total)
{
    extern __shared__ char sm[];
    const int tid  = threadIdx.x;
    const int lane = tid & 31;
    const int wid  = tid >> 5;
    const int warpM = wid >> 2;
    const int warpN = wid & 3;
    const int m0 = blockIdx.y * 128;
    const int n0 = blockIdx.x * 128;

    const __nv_bfloat16* src0 = Ah + (size_t)m0 * 4096;
    const __nv_bfloat16* src1 = Al + (size_t)m0 * 4096;
    const __nv_bfloat16* src2 = Bh + (size_t)n0 * 4096;
    const __nv_bfloat16* src3 = Bl + (size_t)n0 * 4096;

    float acc[4][4][4];
#pragma unroll
    for (int i = 0; i < 4; i++)
#pragma unroll
        for (int j = 0; j < 4; j++)
#pragma unroll
            for (int c = 0; c < 4; c++) acc[i][j][c] = 0.f;

    uint4 pr[8];
    const int q4 = tid & 3;                    // 16B chunk within 64B row

    auto load_regs = [&](int k0c) {
#pragma unroll
        for (int j = 0; j < 8; j++) {
            const __nv_bfloat16* s =
                (j < 2) ? src0 : (j < 4) ? src1 : (j < 6) ? src2 : src3;
            int r = (((j & 1) << 8) | tid) >> 2;     // 0..127
            pr[j] = *(const uint4*)(s + (size_t)r * 4096 + k0c + q4 * 8);
        }
    };

    auto store_regs = [&](int b) {
        char* base = sm + (size_t)b * 4 * PLANE;
#pragma unroll
        for (int j = 0; j < 8; j++) {
            int op = j >> 1;
            int r = (((j & 1) << 8) | tid) >> 2;
            *(uint4*)(base + op * PLANE + r * WST + q4 * 16) = pr[j];
        }
    };

    load_regs(0);
    store_regs(0);
    __syncthreads();

#pragma unroll 1
    for (int it = 0; it < 128; ++it) {
        const int b = it & 1;
        const bool hn = (it + 1) < 128;
        if (hn) load_regs((it + 1) * 32);

        const char* ah  = sm + (size_t)b * 4 * PLANE;
        const char* al  = ah + PLANE;
        const char* bhp = ah + 2 * PLANE;
        const char* blp = ah + 3 * PLANE;

        const int rsel = lane >> 2;
        const int csel = (lane & 3) * 2;

#pragma unroll
        for (int ks = 0; ks < 2; ++ks) {
            const int kb = ks * 16;
            uint32_t fah[4][4], fal[4][4], fbh[4][2], fbl[4][2];
#pragma unroll
            for (int mt = 0; mt < 4; ++mt) {
                int rm = warpM * 64 + mt * 16 + rsel;
                const char* pah = ah + rm * WST + (kb + csel) * 2;
                const char* pal = al + rm * WST + (kb + csel) * 2;
                fah[mt][0] = *(const uint32_t*)(pah);
                fah[mt][1] = *(const uint32_t*)(pah + 8 * WST);
                fah[mt][2] = *(const uint32_t*)(pah + 16);
                fah[mt][3] = *(const uint32_t*)(pah + 8 * WST + 16);
                fal[mt][0] = *(const uint32_t*)(pal);
                fal[mt][1] = *(const uint32_t*)(pal + 8 * WST);
                fal[mt][2] = *(const uint32_t*)(pal + 16);
                fal[mt][3] = *(const uint32_t*)(pal + 8 * WST + 16);
            }
#pragma unroll
            for (int nt = 0; nt < 4; ++nt) {
                int rn = warpN * 32 + nt * 8 + rsel;
                const char* pbh = bhp + rn * WST + (kb + csel) * 2;
                const char* pbl = blp + rn * WST + (kb + csel) * 2;
                fbh[nt][0] = *(const uint32_t*)(pbh);
                fbh[nt][1] = *(const uint32_t*)(pbh + 16);
                fbl[nt][0] = *(const uint32_t*)(pbl);
                fbl[nt][1] = *(const uint32_t*)(pbl + 16);
            }
#pragma unroll
            for (int mt = 0; mt < 4; ++mt)
#pragma unroll
                for (int nt = 0; nt < 4; ++nt) {
                    mma_bf16(acc[mt][nt], fah[mt], fbh[nt]);
                    mma_bf16(acc[mt][nt], fah[mt], fbl[nt]);
                    mma_bf16(acc[mt][nt], fal[mt], fbh[nt]);
                }
        }

        if (hn) store_regs(b ^ 1);
        __syncthreads();
    }

    const int rsel = lane >> 2;
    const int csel = (lane & 3) * 2;
#pragma unroll
    for (int mt = 0; mt < 4; ++mt) {
#pragma unroll
        for (int nt = 0; nt < 4; ++nt) {
            int row = m0 + warpM * 64 + mt * 16 + rsel;
            int col = n0 + warpN * 32 + nt * 8 + csel;
            *(float2*)(C + (size_t)row * N_total + col) =
                make_float2(acc[mt][nt][0], acc[mt][nt][1]);
            *(float2*)(C + (size_t)(row + 8) * N_total + col) =
                make_float2(acc[mt][nt][2], acc[mt][nt][3]);
        }
    }
}

// ---------------------------------------------------------------------------
// RoPE in-place on q (32 heads) and k (8 heads) inside g_qkv.
// ---------------------------------------------------------------------------
__global__ void rope_kernel(float* __restrict__ qkv,
                            const int* __restrict__ positions)
{
    int idx = blockIdx.x * blockDim.x + threadIdx.x;
    const int total = S_LEN * (NQ + NKV) * 64;
    if (idx >= total) return;
    int j = idx & 63;
    int t = idx >> 6;
    int head = t % (NQ + NKV);
    int s = t / (NQ + NKV);
    int col = (head < NQ) ? head * HD : K_OFF + (head - NQ) * HD;
    float* base = qkv + (size_t)s * QKV_N + col;

    float inv = powf(10000.0f, -((float)j) / 64.0f);
    float ang = (float)positions[s] * inv;
    float sn, cs;
    sincosf(ang, &sn, &cs);
    float x1 = base[j];
    float x2 = base[j + 64];
    base[j]      = x1 * cs - x2 * sn;
    base[j + 64] = x2 * cs + x1 * sn;
}

// ---------------------------------------------------------------------------
// Flash attention via mma.sync fp16, 128-row q tiles (KV traffic halved).
// Grid (32, 32): x = q-tile (reversed for tail balance), y = q-head.
// 256 threads = 8 warps; warp w owns q rows [w*16, w*16+16) of the tile.
// QK: fp16 unsplit. PV: P and V hi/lo split fp16.
// Output written directly as bf16 hi/lo planes (O-GEMM A operand).
// ---------------------------------------------------------------------------
#define FQ_ST 272                 // Q/K smem row stride (128 fp16 + 16B pad)
#define FV_ST 144                 // Vt smem row stride (64 fp16 + 16B pad)
#define FLS_Q  0
#define FLS_K  (128 * FQ_ST)                // 34816
#define FLS_VH (FLS_K + 64 * FQ_ST)         // 52224
#define FLS_VL (FLS_VH + 128 * FV_ST)       // 70656
#define FLS_TOT (FLS_VL + 128 * FV_ST)      // 89088

__global__ __launch_bounds__(256) void flash_mma_kernel(
    const float* __restrict__ qkv,
    __nv_bfloat16* __restrict__ Oh, __nv_bfloat16* __restrict__ Ol)
{
    extern __shared__ char fsm[];
    char* Qs = fsm + FLS_Q;
    char* Ks = fsm + FLS_K;
    char* Vh = fsm + FLS_VH;
    char* Vl = fsm + FLS_VL;

    const int tid  = threadIdx.x;
    const int lane = tid & 31;
    const int wid  = tid >> 5;
    const int qb = (gridDim.x - 1 - blockIdx.x) * 128;
    const int qh = blockIdx.y;
    const int kvh = qh >> 2;

    const int rsel = lane >> 2;          // 0..7
    const int cs4  = (lane & 3) * 4;     // byte offset of element 2*(lane&3)

    // Load Q tile [128][128], scale folded, fp32 -> fp16
    {
        const float* qbase = qkv + (size_t)qb * QKV_N + qh * HD;
        for (int i = tid; i < 128 * 64; i += 256) {
            int r = i >> 6, c2 = i & 63;
            float2 v = *(const float2*)(qbase + (size_t)r * QKV_N + c2 * 2);
            __half2 h = __floats2half2_rn(v.x * SCALE_F, v.y * SCALE_F);
            *(uint32_t*)(Qs + r * FQ_ST + c2 * 4) = *(uint32_t*)&h;
        }
    }

    float Of[16][4];
#pragma unroll
    for (int nt = 0; nt < 16; ++nt)
#pragma unroll
        for (int c = 0; c < 4; ++c) Of[nt][c] = 0.f;
    float mi0 = -1e30f, mi1 = -1e30f, li0 = 0.f, li1 = 0.f;

    const int ntiles = (qb >> 6) + 2;
#pragma unroll 1
    for (int t = 0; t < ntiles; ++t) {
        const int kb = t * 64;
        __syncthreads();   // consumers of previous K/V (and Q store) done
        {
            const float* kbase = qkv + (size_t)kb * QKV_N + K_OFF + kvh * HD;
            const float* vbase = qkv + (size_t)kb * QKV_N + V_OFF + kvh * HD;
            for (int i = tid; i < 64 * 64; i += 256) {
                int r = i >> 6, c2 = i & 63;
                float2 kv2 = *(const float2*)(kbase + (size_t)r * QKV_N + c2 * 2);
                __half2 kh = __floats2half2_rn(kv2.x, kv2.y);
                *(uint32_t*)(Ks + r * FQ_ST + c2 * 4) = *(uint32_t*)&kh;

                float2 vv = *(const float2*)(vbase + (size_t)r * QKV_N + c2 * 2);
                __half h0, l0, h1, l1;
                splith(vv.x, h0, l0);
                splith(vv.y, h1, l1);
                int d0 = c2 * 2;
                *(__half*)(Vh + (d0 + 0) * FV_ST + r * 2) = h0;
                *(__half*)(Vh + (d0 + 1) * FV_ST + r * 2) = h1;
                *(__half*)(Vl + (d0 + 0) * FV_ST + r * 2) = l0;
                *(__half*)(Vl + (d0 + 1) * FV_ST + r * 2) = l1;
            }
        }
        __syncthreads();

        // ---- S = Q K^T (warp tile m16 x n64) ----
        float s[8][4];
#pragma unroll
        for (int j = 0; j < 8; ++j)
#pragma unroll
            for (int c = 0; c < 4; ++c) s[j][c] = 0.f;

#pragma unroll
        for (int kk = 0; kk < 8; ++kk) {
            uint32_t a[4];
            const char* pa = Qs + (wid * 16 + rsel) * FQ_ST + kk * 32 + cs4;
            a[0] = *(const uint32_t*)(pa);
            a[1] = *(const uint32_t*)(pa + 8 * FQ_ST);
            a[2] = *(const uint32_t*)(pa + 16);
            a[3] = *(const uint32_t*)(pa + 8 * FQ_ST + 16);
#pragma unroll
            for (int j = 0; j < 8; ++j) {
                uint32_t b[2];
                const char* pb = Ks + (j * 8 + rsel) * FQ_ST + kk * 32 + cs4;
                b[0] = *(const uint32_t*)(pb);
                b[1] = *(const uint32_t*)(pb + 16);
                mma_f16(s[j], a, b);
            }
        }

        // ---- causal mask: only the last two tiles can cross the diagonal ----
        if (t >= ntiles - 2) {
            const int r0 = qb + wid * 16 + rsel;
            const int r1 = r0 + 8;
#pragma unroll
            for (int j = 0; j < 8; ++j) {
                int c0 = kb + j * 8 + (lane & 3) * 2;
                int c1 = c0 + 1;
                if (c0 > r0) s[j][0] = -1e30f;
                if (c1 > r0) s[j][1] = -1e30f;
                if (c0 > r1) s[j][2] = -1e30f;
                if (c1 > r1) s[j][3] = -1e30f;
            }
        }

        // ---- online softmax (rows live in quads) ----
        float m0 = -1e30f, m1 = -1e30f;
#pragma unroll
        for (int j = 0; j < 8; ++j) {
            m0 = fmaxf(m0, fmaxf(s[j][0], s[j][1]));
            m1 = fmaxf(m1, fmaxf(s[j][2], s[j][3]));
        }
        m0 = fmaxf(m0, __shfl_xor_sync(0xffffffffu, m0, 1));
        m0 = fmaxf(m0, __shfl_xor_sync(0xffffffffu, m0, 2));
        m1 = fmaxf(m1, __shfl_xor_sync(0xffffffffu, m1, 1));
        m1 = fmaxf(m1, __shfl_xor_sync(0xffffffffu, m1, 2));

        float mn0 = fmaxf(mi0, m0);
        float mn1 = fmaxf(mi1, m1);
        float corr0 = __expf(mi0 - mn0);
        float corr1 = __expf(mi1 - mn1);
        mi0 = mn0; mi1 = mn1;

        uint32_t ph[4][4], pl[4][4];
        float rs0 = 0.f, rs1 = 0.f;
#pragma unroll
        for (int j = 0; j < 8; ++j) {
            float p0 = __expf(s[j][0] - mn0);
            float p1 = __expf(s[j][1] - mn0);
            float p2 = __expf(s[j][2] - mn1);
            float p3 = __expf(s[j][3] - mn1);
            rs0 += p0 + p1;
            rs1 += p2 + p3;
            __half h0, l0, h1, l1, h2, l2, h3, l3;
            splith(p0, h0, l0); splith(p1, h1, l1);
            splith(p2, h2, l2); splith(p3, h3, l3);
            int kk = j >> 1, w = (j & 1) * 2;
            ph[kk][w + 0] = packh2(h0, h1);
            ph[kk][w + 1] = packh2(h2, h3);
            pl[kk][w + 0] = packh2(l0, l1);
            pl[kk][w + 1] = packh2(l2, l3);
        }
        rs0 += __shfl_xor_sync(0xffffffffu, rs0, 1);
        rs0 += __shfl_xor_sync(0xffffffffu, rs0, 2);
        rs1 += __shfl_xor_sync(0xffffffffu, rs1, 1);
        rs1 += __shfl_xor_sync(0xffffffffu, rs1, 2);
        li0 = li0 * corr0 + rs0;
        li1 = li1 * corr1 + rs1;

#pragma unroll
        for (int nt = 0; nt < 16; ++nt) {
            Of[nt][0] *= corr0; Of[nt][1] *= corr0;
            Of[nt][2] *= corr1; Of[nt][3] *= corr1;
        }

        // ---- O += P @ V (Ph*Vh + Pl*Vh + Ph*Vl) ----
#pragma unroll
        for (int kk = 0; kk < 4; ++kk) {
#pragma unroll
            for (int nt = 0; nt < 16; ++nt) {
                const char* pbh = Vh + (nt * 8 + rsel) * FV_ST + kk * 32 + cs4;
                const char* pbl = Vl + (nt * 8 + rsel) * FV_ST + kk * 32 + cs4;
                uint32_t bh[2], bl[2];
                bh[0] = *(const uint32_t*)(pbh);
                bh[1] = *(const uint32_t*)(pbh + 16);
                bl[0] = *(const uint32_t*)(pbl);
                bl[1] = *(const uint32_t*)(pbl + 16);
                mma_f16(Of[nt], ph[kk], bh);
                mma_f16(Of[nt], pl[kk], bh);
                mma_f16(Of[nt], ph[kk], bl);
            }
        }
    }

    // ---- epilogue: normalize and write hi/lo bf16 planes ----
    const float inv0 = 1.0f / li0;
    const float inv1 = 1.0f / li1;
    const int row0 = qb + wid * 16 + rsel;
    const int row1 = row0 + 8;
#pragma unroll
    for (int nt = 0; nt < 16; ++nt) {
        int col = qh * HD + nt * 8 + (lane & 3) * 2;
        uint32_t h, l;
        split2(Of[nt][0] * inv0, Of[nt][1] * inv0, h, l);
        *(uint32_t*)(Oh + (size_t)row0 * HID + col) = h;
        *(uint32_t*)(Ol + (size_t)row0 * HID + col) = l;
        split2(Of[nt][2] * inv1, Of[nt][3] * inv1, h, l);
        *(uint32_t*)(Oh + (size_t)row1 * HID + col) = h;
        *(uint32_t*)(Ol + (size_t)row1 * HID + col) = l;
    }
}

// ---------------------------------------------------------------------------
// launch
// ---------------------------------------------------------------------------
extern "C" void kernel_launch(void* const* d_in, const int* in_sizes, int n_in,
                              void* d_out, int out_size)
{
    const int*   positions = (const int*)d_in[0];
    const float* hidden    = (const float*)d_in[1];
    const float* w_qkv     = (const float*)d_in[2];
    const float* w_o       = (const float*)d_in[3];
    float*       out       = (float*)d_out;

    float *qkv = nullptr;
    __nv_bfloat16 *hidh = nullptr, *hidl = nullptr, *ath = nullptr, *atl = nullptr;
    __nv_bfloat16 *bhq = nullptr, *blq = nullptr, *bho = nullptr, *blo = nullptr;
    cudaGetSymbolAddress((void**)&qkv,  g_qkv);
    cudaGetSymbolAddress((void**)&hidh, g_hid_h);
    cudaGetSymbolAddress((void**)&hidl, g_hid_l);
    cudaGetSymbolAddress((void**)&ath,  g_at_h);
    cudaGetSymbolAddress((void**)&atl,  g_at_l);
    cudaGetSymbolAddress((void**)&bhq,  g_bh_qkv);
    cudaGetSymbolAddress((void**)&blq,  g_bl_qkv);
    cudaGetSymbolAddress((void**)&bho,  g_bh_o);
    cudaGetSymbolAddress((void**)&blo,  g_bl_o);

    // 0) weight transpose+split, and hidden split
    transpose_convert_kernel<<<dim3(QKV_N / 32, HID / 32), dim3(32, 8)>>>(
        w_qkv, bhq, blq, HID, QKV_N);
    transpose_convert_kernel<<<dim3(HID / 32, HID / 32), dim3(32, 8)>>>(
        w_o, bho, blo, HID, HID);
    split_a_kernel<<<(S_LEN * HID / 2 + 255) / 256, 256>>>(hidden, hidh, hidl);

    cudaFuncSetAttribute(tc_gemm_kernel,
                         cudaFuncAttributeMaxDynamicSharedMemorySize, SM_TOT);

    // 1) QKV projection (mma.sync split-bf16)
    tc_gemm_kernel<<<dim3(QKV_N / 128, S_LEN / 128), 256, SM_TOT>>>(
        hidh, hidl, bhq, blq, qkv, QKV_N);

    // 2) RoPE
    {
        int total = S_LEN * (NQ + NKV) * 64;
        rope_kernel<<<(total + 255) / 256, 256>>>(qkv, positions);
    }

    // 3) Flash attention (mma.sync fp16, 128-row tiles, split P/V)
    {
        cudaFuncSetAttribute(flash_mma_kernel,
                             cudaFuncAttributeMaxDynamicSharedMemorySize,
                             FLS_TOT);
        flash_mma_kernel<<<dim3(S_LEN / 128, NQ), 256, FLS_TOT>>>(qkv, ath, atl);
    }

    // 4) Output projection (mma.sync split-bf16)
    tc_gemm_kernel<<<dim3(HID / 128, S_LEN / 128), 256, SM_TOT>>>(
        ath, atl, bho, blo, out, HID);
}